// round 17
// baseline (speedup 1.0000x reference)
#include <cuda_runtime.h>
#include <cuda_fp16.h>
#include <cuda_bf16.h>
#include <math.h>

// ---------------- problem constants ------------------------------------------
#define NQ      64
#define KDIM    768
#define TILE_M  128                 // bank rows per CTA tile
#define CHUNK_K 64                  // K elems per chunk (fp16 row = 128 B)
#define NCHUNK  (KDIM / CHUNK_K)    // 12
#define MAXROWS 500000
#define MAXTILES ((MAXROWS + TILE_M - 1) / TILE_M)   // 3907
#define TPT     4                   // candidates kept per (q, tile)
#define CAND    16                  // candidates exactly rescored per query
#define TB_PAD  136                 // transpose buffer row pitch (bf16 elems)

// ---------------- smem layout (score kernel): 50 KB -> 3 CTAs/SM -------------
#define SM_INVN 0                                   // float[128]
#define SM_BUF0 1024                                // Q 8KB + B 16KB
#define SM_BUF1 (SM_BUF0 + 24576)                   // 25600
#define SM_TB   1024                                // epilogue transpose (overlay buf0)
#define SM_CV   SM_BUF1                             // float[256*4] (overlay buf1)
#define SM_CI   (SM_BUF1 + 4096)                    // int[256*4]
#define SCORE_SMEM (SM_BUF1 + 24576)                // 50176 (3x = 150528 < 227KB)

// ---------------- device scratch (allocation-free rule) ----------------------
__device__ __align__(16) float  g_qn [NQ * KDIM];                     // fp32 normalized queries
__device__ __align__(16) char   g_qstage[NCHUNK * 8192];              // swizzled per-chunk Q (fp16)
__device__ __align__(16) float g_ctv[(size_t)NQ * MAXTILES * TPT];    // per-tile cand vals
__device__ __align__(16) int   g_cti[(size_t)NQ * MAXTILES * TPT];    // per-tile cand ids

// ---------------- kernel 1: normalize queries + staged-layout fp16 copy ------
__global__ void norm_q_kernel(const float* __restrict__ q) {
    __shared__ float red[256];
    int qi = blockIdx.x, tid = threadIdx.x;
    const float* qr = q + qi * KDIM;
    float v0 = qr[tid], v1 = qr[tid + 256], v2 = qr[tid + 512];
    red[tid] = v0 * v0 + v1 * v1 + v2 * v2;
    __syncthreads();
    for (int st = 128; st > 0; st >>= 1) {
        if (tid < st) red[tid] += red[tid + st];
        __syncthreads();
    }
    float inv = 1.0f / fmaxf(sqrtf(red[0]), 1e-12f);
    float o[3] = {v0 * inv, v1 * inv, v2 * inv};
    g_qn[qi * KDIM + tid      ] = o[0];
    g_qn[qi * KDIM + tid + 256] = o[1];
    g_qn[qi * KDIM + tid + 512] = o[2];
    // write fp16 into the exact swizzled per-chunk staging layout
    #pragma unroll
    for (int j = 0; j < 3; j++) {
        const int k = tid + j * 256;
        const int c = k >> 6, kr = k & 63;
        const int off = c * 8192 + qi * 128 + (((kr >> 2) * 8) ^ ((qi & 7) << 4)) + (kr & 3) * 2;
        *(__half*)(g_qstage + off) = __float2half(o[j]);
    }
}

// ---------------- kernel 2: mma score (3 CTAs/SM) + fused per-tile top-4 -----
#define ROWSTRIDE (16 * KDIM)       // fp32 elems between this thread's row slots

__device__ __forceinline__ void ld_bank(float4 (&f)[8], const float* rp0,
                                        unsigned vmask, int c) {
    #pragma unroll
    for (int p = 0; p < 8; p++) {
        if ((vmask >> p) & 1) f[p] = *(const float4*)(rp0 + p * ROWSTRIDE + c * CHUNK_K);
        else                  f[p] = make_float4(0.f, 0.f, 0.f, 0.f);
    }
}

__device__ __forceinline__ void ldsm_x4(unsigned& r0, unsigned& r1, unsigned& r2,
                                        unsigned& r3, unsigned addr) {
    asm volatile("ldmatrix.sync.aligned.m8n8.x4.shared.b16 {%0,%1,%2,%3}, [%4];"
                 : "=r"(r0), "=r"(r1), "=r"(r2), "=r"(r3) : "r"(addr));
}

__device__ __forceinline__ unsigned s2u(const void* p) {
    unsigned a;
    asm("{ .reg .u64 t; cvta.to.shared.u64 t, %1; cvt.u32.u64 %0, t; }" : "=r"(a) : "l"(p));
    return a;
}

__global__ __launch_bounds__(256, 3)
void score_kernel(const float* __restrict__ bank, int nrows) {
    extern __shared__ char smem[];
    const unsigned sbase = s2u(smem);
    const int tid = threadIdx.x, warp = tid >> 5, lane = tid & 31;
    const int lr = lane >> 4, lc = lane & 15;

    // ---- global load mapping: 16 lanes per row, 8 row-slots, one base ptr ----
    const int rowbase = warp * 2 + lr;              // row slot p lives at rowbase + 16p
    const float* rp0 = bank + ((long long)blockIdx.x * TILE_M + rowbase) * KDIM + lc * 4;
    unsigned vmask = 0;
    #pragma unroll
    for (int p = 0; p < 8; p++)
        if ((long long)blockIdx.x * TILE_M + rowbase + p * 16 < (long long)nrows)
            vmask |= 1u << p;
    float ssq[8];
    #pragma unroll
    for (int p = 0; p < 8; p++) ssq[p] = 0.f;
    const int scol = (lc * 8) ^ ((rowbase & 7) << 4);   // row&7 is p-invariant

    // ---- mma thread constants (R14-proven layout) -----------------------------
    const int qbase = (warp & 3) * 16;          // m (query) strip
    const int nbase = (warp >> 2) * 64;         // n (bank row) strip
    const int arow  = qbase + ((lane >> 3) & 1) * 8 + (lane & 7);
    const int axtr  = (lane >> 4) * 16;
    const int brow0 = nbase + ((lane >> 4) & 1) * 8 + (lane & 7);   // + pair*16
    const int bxtr  = ((lane >> 3) & 1) * 16;
    const int lsw   = (lane & 7) << 4;

    float acc[8][4];
    #pragma unroll
    for (int i = 0; i < 8; i++)
        #pragma unroll
        for (int j = 0; j < 4; j++) acc[i][j] = 0.f;

    float4 f[8];
    ld_bank(f, rp0, vmask, 0);          // prologue: chunk 0 in flight

    for (int c = 0; c < NCHUNK; c++) {
        const unsigned buf = sbase + ((c & 1) ? SM_BUF1 : SM_BUF0);
        char* bufp = smem + ((c & 1) ? SM_BUF1 : SM_BUF0);
        // stage Q chunk (straight copy of pre-swizzled L2-hot slice; no prefetch
        // regs — 3 CTA domains cover the L2 latency)
        {
            const uint4* src = (const uint4*)(g_qstage) + c * 512;
            ((uint4*)bufp)[tid * 2    ] = src[tid * 2];
            ((uint4*)bufp)[tid * 2 + 1] = src[tid * 2 + 1];
        }
        // stage B chunk: convert + STS (waits on its LDGs via scoreboard)
        char* stb = bufp + 8192 + rowbase * 128 + scol;
        #pragma unroll
        for (int p = 0; p < 8; p++) {
            float4 fv = f[p];
            ssq[p] += fv.x * fv.x + fv.y * fv.y + fv.z * fv.z + fv.w * fv.w;
            __half2 p0 = __floats2half2_rn(fv.x, fv.y);
            __half2 p1 = __floats2half2_rn(fv.z, fv.w);
            uint2 u;
            u.x = *(unsigned*)&p0;
            u.y = *(unsigned*)&p1;
            *(uint2*)(stb + p * 2048) = u;
        }
        __syncthreads();   // single sync: stage(c) visible; double-buffer makes the
                           // fast-warp stage(c+1) (other buffer) safe vs mma(c).

        // next chunk's bank loads issued before mma work (hidden behind mma)
        if (c + 1 < NCHUNK) ld_bank(f, rp0, vmask, c + 1);

        // mma over chunk c: 4 k16 steps x 8 ntiles
        const unsigned qb = buf;
        const unsigned bb = buf + 8192;
        #pragma unroll
        for (int kk = 0; kk < 4; kk++) {
            unsigned a0, a1, a2, a3;
            ldsm_x4(a0, a1, a2, a3,
                    qb + arow * 128 + ((kk * 32 + axtr) ^ lsw));
            #pragma unroll
            for (int pair = 0; pair < 4; pair++) {
                unsigned b0, b1, b2, b3;
                ldsm_x4(b0, b1, b2, b3,
                        bb + (brow0 + pair * 16) * 128 + ((kk * 32 + bxtr) ^ lsw));
                asm volatile(
                    "mma.sync.aligned.m16n8k16.row.col.f32.f16.f16.f32 "
                    "{%0,%1,%2,%3}, {%4,%5,%6,%7}, {%8,%9}, {%0,%1,%2,%3};\n"
                    : "+f"(acc[pair*2][0]), "+f"(acc[pair*2][1]),
                      "+f"(acc[pair*2][2]), "+f"(acc[pair*2][3])
                    : "r"(a0), "r"(a1), "r"(a2), "r"(a3), "r"(b0), "r"(b1));
                asm volatile(
                    "mma.sync.aligned.m16n8k16.row.col.f32.f16.f16.f32 "
                    "{%0,%1,%2,%3}, {%4,%5,%6,%7}, {%8,%9}, {%0,%1,%2,%3};\n"
                    : "+f"(acc[pair*2+1][0]), "+f"(acc[pair*2+1][1]),
                      "+f"(acc[pair*2+1][2]), "+f"(acc[pair*2+1][3])
                    : "r"(a0), "r"(a1), "r"(a2), "r"(a3), "r"(b2), "r"(b3));
            }
        }
    }

    // ---- row inverse norms (16 lanes share a row) -----------------------------
    float* invn = (float*)(smem + SM_INVN);
    #pragma unroll
    for (int p = 0; p < 8; p++) {
        float s = ssq[p];
        s += __shfl_xor_sync(0xffffffffu, s, 1);
        s += __shfl_xor_sync(0xffffffffu, s, 2);
        s += __shfl_xor_sync(0xffffffffu, s, 4);
        s += __shfl_xor_sync(0xffffffffu, s, 8);
        if (lc == 0) invn[p * 16 + rowbase] = 1.0f / fmaxf(sqrtf(s), 1e-12f);
    }
    __syncthreads();   // invn ready AND all warps past final mma (buffer reuse safe)

    // ---- epilogue 1: regs -> smem transpose buffer [q][TB_PAD] bf16 -----------
    {
        __nv_bfloat16* tb = (__nv_bfloat16*)(smem + SM_TB);
        const int q0 = qbase + (lane >> 2);
        #pragma unroll
        for (int nt = 0; nt < 8; nt++) {
            const int r0 = nbase + nt * 8 + (lane & 3) * 2;
            const float i0 = invn[r0], i1 = invn[r0 + 1];
            __nv_bfloat162 v01 = __floats2bfloat162_rn(acc[nt][0] * i0, acc[nt][1] * i1);
            __nv_bfloat162 v23 = __floats2bfloat162_rn(acc[nt][2] * i0, acc[nt][3] * i1);
            *(__nv_bfloat162*)&tb[ q0      * TB_PAD + r0] = v01;
            *(__nv_bfloat162*)&tb[(q0 + 8) * TB_PAD + r0] = v23;
        }
    }
    __syncthreads();

    // ---- epilogue 2: fused per-(q,tile) top-4 extraction ----------------------
    {
        const __nv_bfloat16* tb = (const __nv_bfloat16*)(smem + SM_TB);
        float* cv = (float*)(smem + SM_CV);
        int*   ci = (int*)(smem + SM_CI);
        const int q = tid >> 2, seg = tid & 3;

        float v4[TPT]; int i4[TPT];
        #pragma unroll
        for (int j = 0; j < TPT; j++) { v4[j] = -3.4e38f; i4[j] = 0x7fffffff; }
        #pragma unroll 8
        for (int r = 0; r < 32; r++) {
            float v = __bfloat162float(tb[q * TB_PAD + seg * 32 + r]);
            if (v > v4[TPT - 1]) {
                int j = TPT - 1;
                while (j > 0 && v > v4[j - 1]) { v4[j] = v4[j-1]; i4[j] = i4[j-1]; j--; }
                v4[j] = v; i4[j] = seg * 32 + r;
            }
        }
        #pragma unroll
        for (int j = 0; j < TPT; j++) { cv[tid * TPT + j] = v4[j]; ci[tid * TPT + j] = i4[j]; }
        __syncthreads();

        if (seg == 0) {
            float m4[TPT]; int mi[TPT];
            #pragma unroll
            for (int j = 0; j < TPT; j++) { m4[j] = -3.4e38f; mi[j] = 0x7fffffff; }
            for (int s = 0; s < 4; s++)
                #pragma unroll
                for (int j = 0; j < TPT; j++) {
                    float v = cv[(q * 4 + s) * TPT + j];
                    int  idx = ci[(q * 4 + s) * TPT + j];
                    if (v > m4[TPT - 1]) {
                        int t = TPT - 1;
                        while (t > 0 && v > m4[t - 1]) { m4[t] = m4[t-1]; mi[t] = mi[t-1]; t--; }
                        m4[t] = v; mi[t] = idx;
                    }
                }
            const long long tb0 = (long long)blockIdx.x * TILE_M;
            const size_t base = ((size_t)q * gridDim.x + blockIdx.x) * TPT;
            #pragma unroll
            for (int j = 0; j < TPT; j++) {
                g_ctv[base + j] = m4[j];
                g_cti[base + j] = (mi[j] == 0x7fffffff) ? 0x7fffffff : (int)(tb0 + mi[j]);
            }
        }
    }
}

// ---------------- kernel 3: merge candidates + exact fp32 rescore + output ---
__global__ __launch_bounds__(256, 1)
void merge_final_kernel(const float* __restrict__ bank, float* __restrict__ out,
                        int nrows, int k, int ntiles) {
    __shared__ float sv[256 * CAND];
    __shared__ int   si[256 * CAND];
    __shared__ float rv[CAND];
    __shared__ int   sid[CAND];
    const int q = blockIdx.x, tid = threadIdx.x;
    const int lane = tid & 31, warp = tid >> 5;

    // per-thread top-16 over this query's candidate stream (id-aware comparator)
    float v[CAND]; int id[CAND];
    #pragma unroll
    for (int i = 0; i < CAND; i++) { v[i] = -3.4e38f; id[i] = 0x7fffffff; }
    const size_t qbase = (size_t)q * ntiles * TPT;
    const int total = ntiles * TPT;
    for (int i = tid; i < total; i += 256) {
        float nv = g_ctv[qbase + i];
        int   ni = g_cti[qbase + i];
        if (ni >= nrows) continue;
        float lv = v[CAND - 1]; int li = id[CAND - 1];
        if (nv < lv || (nv == lv && ni >= li)) continue;
        int j = CAND - 1;
        while (j > 0 && (nv > v[j - 1] || (nv == v[j - 1] && ni < id[j - 1]))) {
            v[j] = v[j - 1]; id[j] = id[j - 1]; j--;
        }
        v[j] = nv; id[j] = ni;
    }
    #pragma unroll
    for (int i = 0; i < CAND; i++) { sv[tid * CAND + i] = v[i]; si[tid * CAND + i] = id[i]; }
    __syncthreads();

    // tree merge of sorted-16 lists (bounded reads)
    for (int st = 128; st > 0; st >>= 1) {
        if (tid < st) {
            const int ao = tid * CAND, bo = (tid + st) * CAND;
            float ov[CAND]; int oi[CAND];
            int ia = 0, ib = 0;
            #pragma unroll
            for (int o = 0; o < CAND; o++) {
                float va = (ia < CAND) ? sv[ao + ia] : -3.4e38f;
                float vb = (ib < CAND) ? sv[bo + ib] : -3.4e38f;
                int   xa = si[ao + min(ia, CAND - 1)];
                int   xb = si[bo + min(ib, CAND - 1)];
                bool takeA;
                if (va > vb) takeA = true;
                else if (va < vb) takeA = false;
                else takeA = (xa <= xb);
                if (takeA) { ov[o] = va; oi[o] = xa; ia++; }
                else       { ov[o] = vb; oi[o] = xb; ib++; }
            }
            #pragma unroll
            for (int o = 0; o < CAND; o++) { sv[ao + o] = ov[o]; si[ao + o] = oi[o]; }
        }
        __syncthreads();
    }

    if (tid < CAND) sid[tid] = si[tid];
    __syncthreads();

    // exact fp32 rescore of the 16 survivors
    for (int c = warp; c < CAND; c += 8) {
        const int cid = sid[c];
        float val = -3.4e38f;
        if (cid >= 0 && cid < nrows) {
            const float4* b4 = (const float4*)(bank + (long long)cid * KDIM);
            const float4* q4 = (const float4*)(g_qn + q * KDIM);
            float dot = 0.f, ss = 0.f;
            #pragma unroll
            for (int i = 0; i < 6; i++) {
                float4 bb = b4[lane + i * 32];
                float4 qq = q4[lane + i * 32];
                dot = fmaf(qq.x, bb.x, fmaf(qq.y, bb.y, fmaf(qq.z, bb.z, fmaf(qq.w, bb.w, dot))));
                ss  = fmaf(bb.x, bb.x, fmaf(bb.y, bb.y, fmaf(bb.z, bb.z, fmaf(bb.w, bb.w, ss))));
            }
            #pragma unroll
            for (int o = 16; o; o >>= 1) {
                dot += __shfl_xor_sync(0xffffffffu, dot, o);
                ss  += __shfl_xor_sync(0xffffffffu, ss,  o);
            }
            val = dot / fmaxf(sqrtf(ss), 1e-12f);
        }
        if (lane == 0) rv[c] = val;
    }
    __syncthreads();

    if (tid == 0) {
        bool used[CAND];
        #pragma unroll
        for (int i = 0; i < CAND; i++) used[i] = false;
        for (int j = 0; j < k; j++) {
            int best = -1; float bvv = -3.4e38f;
            for (int i = 0; i < CAND; i++) {
                if (used[i]) continue;
                if (best < 0 || rv[i] > bvv ||
                    (rv[i] == bvv && sid[i] < sid[best])) { bvv = rv[i]; best = i; }
            }
            used[best] = true;
            out[q * k + j]          = bvv;
            out[NQ * k + q * k + j] = (float)sid[best];
        }
    }
}

// ---------------- launch -----------------------------------------------------
extern "C" void kernel_launch(void* const* d_in, const int* in_sizes, int n_in,
                              void* d_out, int out_size) {
    const float* query = (const float*)d_in[0];
    const float* bank  = (const float*)d_in[1];
    const int nrows = in_sizes[1] / KDIM;
    const int k = out_size / (2 * NQ);

    cudaFuncSetAttribute(score_kernel, cudaFuncAttributeMaxDynamicSharedMemorySize, SCORE_SMEM);

    norm_q_kernel<<<NQ, 256>>>(query);

    const int ntiles = (nrows + TILE_M - 1) / TILE_M;
    score_kernel<<<ntiles, 256, SCORE_SMEM>>>(bank, nrows);

    merge_final_kernel<<<NQ, 256>>>(bank, (float*)d_out, nrows, k, ntiles);
}